// round 10
// baseline (speedup 1.0000x reference)
#include <cuda_runtime.h>
#include <math.h>

#define IMG     256
#define NFACE   512
#define NVERT   4096
#define NPIX    (IMG * IMG)
#define NCHUNK  4
#define FPC     (NFACE / NCHUNK)     // 128 faces per chunk
#define NGRP    (FPC / 4)            // 32 groups of 4 faces per chunk
#define PPT     4                    // pixels per thread (same column)
#define RBLK    64                   // render blocks per chunk (x-dim)
#define CBLK    64                   // combine blocks (4 px/thread)

// Scratch (no cudaMalloc allowed)
__device__ float2 g_pv[NVERT];            // projected (x,y) per vertex
__device__ float4 g_coef[NFACE * 3];      // per-face, per-edge affine coeffs (A,B,C,_), log2-scaled
__device__ float  g_S[NCHUNK * NPIX];     // partial log2-domain sums
__device__ float  g_partial[CBLK];        // per-block loss partials

__device__ __forceinline__ float ex2f(float x) {
    float r; asm("ex2.approx.ftz.f32 %0, %1;" : "=f"(r) : "f"(x)); return r;
}
__device__ __forceinline__ float lg2f(float x) {
    float r; asm("lg2.approx.ftz.f32 %0, %1;" : "=f"(r) : "f"(x)); return r;
}

struct Cam {
    float ex, ey, ez;
    float r00, r01, r02, r10, r11, r12, r20, r21, r22;
    float tanv;
};

// ---------------- Kernel 1: merged setup (vertex transform + face coefficients) ----
// Single block, 512 threads. Phase 1: 8 verts/thread (look_at + perspective).
// Phase 2 (after block barrier): 1 face/thread -> 3 edge coefficient float4s.
__global__ void __launch_bounds__(512) k_setup(const float* __restrict__ verts,
                                               const int* __restrict__ faces, Cam cam) {
    const int tid = threadIdx.x;

    // Phase 1: transform vertices
#pragma unroll
    for (int r = 0; r < NVERT / 512; r++) {
        int i = r * 512 + tid;
        float vx = verts[i * 3 + 0] - cam.ex;
        float vy = verts[i * 3 + 1] - cam.ey;
        float vz = verts[i * 3 + 2] - cam.ez;
        float X = cam.r00 * vx + cam.r01 * vy + cam.r02 * vz;
        float Y = cam.r10 * vx + cam.r11 * vy + cam.r12 * vz;
        float Z = cam.r20 * vx + cam.r21 * vy + cam.r22 * vz;
        float denom = Z * cam.tanv + 1e-8f;
        g_pv[i] = make_float2(X / denom, Y / denom);
    }
    __syncthreads();

    // Phase 2: per-face edge coefficients
    // d_edge(px,py) * inv_len * sgn * (1/sigma) * log2(e)  ==  A*px + B*py + C
    const int f = tid;
    int i0 = faces[f * 3 + 0];
    int i1 = faces[f * 3 + 1];
    int i2 = faces[f * 3 + 2];
    float2 a = g_pv[i0], b = g_pv[i1], c = g_pv[i2];

    float area = (b.x - a.x) * (c.y - a.y) - (b.y - a.y) * (c.x - a.x);
    float sgn = (area >= 0.0f) ? 1.0f : -1.0f;

    const float SCALE = 144.26950408889634f;  // (1/0.01) * log2(e)

    float2 p0s[3] = { a, b, c };
    float2 p1s[3] = { b, c, a };
#pragma unroll
    for (int e = 0; e < 3; e++) {
        float exx = p1s[e].x - p0s[e].x;
        float eyy = p1s[e].y - p0s[e].y;
        float il = rsqrtf(exx * exx + eyy * eyy + 1e-8f);
        float k = il * sgn * SCALE;
        // d = ex*(py-p0y) - ey*(px-p0x)  ->  A = -ey*k (on px), B = ex*k (on py), C
        g_coef[f * 3 + e] = make_float4(-eyy * k, exx * k,
                                        (eyy * p0s[e].x - exx * p0s[e].y) * k, 0.0f);
    }
}

// ---------------- Kernel 2: render — partial S over one face chunk ----------------
// Thread owns 4 pixels in one column. Faces processed in GROUPS OF 4:
//   y_f = min3(affine edge dists), clamped at CLMP (preserves reference alpha clip);
//   t_f = 2^y_f ;  S += lg2( Π_f (1+t_f) )  via balanced fma tree (1 LG2 per 4 faces).
// Product bounded by 2^79.7 < fp32 max (each t <= 2^19.91): no overflow.
// Only B (the py coefficient) stays live across the pixel loop -> small register set.
__global__ void __launch_bounds__(256) k_render(int unused) {
    __shared__ float4 sc[FPC * 3];    // 6 KB, broadcast-read

    const int tid   = threadIdx.x;
    const int chunk = blockIdx.y;

    for (int i = tid; i < FPC * 3; i += 256)
        sc[i] = g_coef[chunk * FPC * 3 + i];
    __syncthreads();

    const int T   = blockIdx.x * 256 + tid;      // 0..16383
    const int col = T & 255;
    const int rg  = T >> 8;                      // row group 0..63
    const float px = (col + 0.5f) * (2.0f / 256.0f) - 1.0f;
    float py[PPT];
#pragma unroll
    for (int i = 0; i < PPT; i++)
        py[i] = -(((rg * PPT + i) + 0.5f) * (2.0f / 256.0f) - 1.0f);

    const float CLMP = 19.912537f;   // -log2(1 - fp32(1-1e-6)) = 24 - log2(17)

    float S[PPT] = {0.f, 0.f, 0.f, 0.f};

    // unroll 2: bounds SASS body ~6.5 KB (inside L0+L1.5 I$) while doubling
    // independent work to cover the EX2->FMA-tree->LG2 dependent chain.
#pragma unroll 2
    for (int g = 0; g < NGRP; g++) {
        // 4 faces x 3 edges: hoist u = A*px + C; keep only B (cy) live afterwards
        float cy[12];
        float u[12];
#pragma unroll
        for (int e = 0; e < 12; e++) {
            float4 c = sc[g * 12 + e];
            cy[e] = c.y;
            u[e]  = fmaf(c.x, px, c.z);
        }
#pragma unroll
        for (int i = 0; i < PPT; i++) {
            float t[4];
#pragma unroll
            for (int f = 0; f < 4; f++) {
                float d0 = fmaf(cy[f * 3 + 0], py[i], u[f * 3 + 0]);
                float d1 = fmaf(cy[f * 3 + 1], py[i], u[f * 3 + 1]);
                float d2 = fmaf(cy[f * 3 + 2], py[i], u[f * 3 + 2]);
                float y  = fminf(fminf(d0, d1), d2);
                t[f] = ex2f(fminf(y, CLMP));     // 2^y (flushes to 0 for y << 0)
            }
            float P01 = fmaf(t[0], t[1], t[0] + t[1]);   // (1+t0)(1+t1) - 1
            float P23 = fmaf(t[2], t[3], t[2] + t[3]);
            float P   = fmaf(P01, P23, P01 + P23);       // Π(1+t) - 1
            S[i] += lg2f(1.0f + P);
        }
    }

#pragma unroll
    for (int i = 0; i < PPT; i++)
        g_S[chunk * NPIX + (rg * PPT + i) * IMG + col] = S[i];
}

// ---------------- Kernel 3: combine chunks, loss, per-block reduce ----------------
// 64 blocks x 256 threads, 4 pixels per thread.
__global__ void __launch_bounds__(256) k_combine(const float* __restrict__ imgref) {
    __shared__ float red[256];
    int tid = threadIdx.x;
    float acc = 0.0f;
#pragma unroll
    for (int r = 0; r < 4; r++) {
        int pix = (blockIdx.x * 4 + r) * 256 + tid;
        float S = g_S[pix] + g_S[NPIX + pix] + g_S[2 * NPIX + pix] + g_S[3 * NPIX + pix];
        float sil = 1.0f - ex2f(-S);
        float d = sil - imgref[pix];
        acc = fmaf(d, d, acc);
    }
    red[tid] = acc;
    __syncthreads();
#pragma unroll
    for (int s = 128; s >= 32; s >>= 1) {
        if (tid < s) red[tid] += red[tid + s];
        __syncthreads();
    }
    if (tid < 32) {
        float v = red[tid];
#pragma unroll
        for (int o = 16; o > 0; o >>= 1)
            v += __shfl_down_sync(0xFFFFFFFF, v, o);
        if (tid == 0) g_partial[blockIdx.x] = v;
    }
}

// ---------------- Kernel 4: final deterministic reduction (64 partials) ----------
__global__ void k_final(float* __restrict__ out) {
    int tid = threadIdx.x;            // 64 threads
    float v = g_partial[tid];
    __shared__ float w[2];
#pragma unroll
    for (int o = 16; o > 0; o >>= 1)
        v += __shfl_down_sync(0xFFFFFFFF, v, o);
    if ((tid & 31) == 0) w[tid >> 5] = v;
    __syncthreads();
    if (tid == 0) out[0] = w[0] + w[1];
}

extern "C" void kernel_launch(void* const* d_in, const int* in_sizes, int n_in,
                              void* d_out, int out_size) {
    const float* verts = nullptr;
    const int*   faces = nullptr;
    const float* img   = nullptr;
    for (int i = 0; i < n_in; i++) {
        if (in_sizes[i] == NVERT * 3)      verts = (const float*)d_in[i];
        else if (in_sizes[i] == NFACE * 3) faces = (const int*)d_in[i];
        else if (in_sizes[i] == NPIX)      img   = (const float*)d_in[i];
    }

    // Camera constants (host-side double; deviation vs fp32 reference ~1e-7)
    double dist = 2.732, el = 0.0, az = 90.0 * M_PI / 180.0;
    double ex = dist * cos(el) * sin(az);
    double ey = dist * sin(el);
    double ez = -dist * cos(el) * cos(az);
    double zx = -ex, zy = -ey, zz = -ez;
    double zn = sqrt(zx * zx + zy * zy + zz * zz) + 1e-8;
    zx /= zn; zy /= zn; zz /= zn;
    double xx = zz, xy = 0.0, xz = -zx;                 // cross(up, z)
    double xn = sqrt(xx * xx + xy * xy + xz * xz) + 1e-8;
    xx /= xn; xy /= xn; xz /= xn;
    double yx = zy * xz - zz * xy;                      // cross(z, x)
    double yy = zz * xx - zx * xz;
    double yz = zx * xy - zy * xx;
    double yn = sqrt(yx * yx + yy * yy + yz * yz) + 1e-8;
    yx /= yn; yy /= yn; yz /= yn;

    Cam cam;
    cam.ex = (float)ex; cam.ey = (float)ey; cam.ez = (float)ez;
    cam.r00 = (float)xx; cam.r01 = (float)xy; cam.r02 = (float)xz;
    cam.r10 = (float)yx; cam.r11 = (float)yy; cam.r12 = (float)yz;
    cam.r20 = (float)zx; cam.r21 = (float)zy; cam.r22 = (float)zz;
    cam.tanv = (float)tan(30.0 * M_PI / 180.0);

    k_setup<<<1, 512>>>(verts, faces, cam);
    dim3 rg(RBLK, NCHUNK);
    k_render<<<rg, 256>>>(0);
    k_combine<<<CBLK, 256>>>(img);
    k_final<<<1, 64>>>((float*)d_out);
}